// round 12
// baseline (speedup 1.0000x reference)
#include <cuda_runtime.h>
#include <cuda_fp16.h>
#include <cstdint>
#include <math.h>
#include <float.h>

#define NN 50000
#define NE 800000
#define D 128
#define PH 136            // smem pitch in halves
#define NBLK 196
#define ETILES 5          // edge tiles (128 edges each) per block; 6250/5 = 1250 blocks

__device__ __half g_feat_h[NN * D];
__device__ __half g_S[NN * D];
__device__ __half g_Dt[NN * D];
__device__ __half g_H[NN * D];
__device__ __half g_H2[NN * D];
__device__ __half g_neigh[NN * D];
__device__ __half g_neigh2[NN * D];
__device__ int   g_deg[NN];
__device__ int   g_rowptr[NN + 1];
__device__ int   g_cursor[NN];
__device__ int   g_scantmp[NN];
__device__ int   g_bsum[256];
__device__ int   g_sbuf[NE];
__device__ int   g_dbuf[NE];
__device__ float g_score[NE];
__device__ float g_WS[D * D];
__device__ float g_WD[D * D];
__device__ float g_be[D];

__device__ __forceinline__ float gelu_f(float x) {
    return 0.5f * x * (1.0f + erff(x * 0.70710678118654752f));
}
__device__ __forceinline__ uint32_t pk2(float x, float y) {
    __half2 h = __floats2half2_rn(x, y);
    return *(uint32_t*)&h;
}
__device__ __forceinline__ float2 up2(uint32_t u) {
    return __half22float2(*(__half2*)&u);
}
__device__ __forceinline__ void mma16(float* c, uint32_t a0, uint32_t a1, uint32_t a2,
                                      uint32_t a3, uint32_t b0, uint32_t b1) {
    asm volatile("mma.sync.aligned.m16n8k16.row.col.f32.f16.f16.f32 "
                 "{%0,%1,%2,%3},{%4,%5,%6,%7},{%8,%9},{%0,%1,%2,%3};"
                 : "+f"(c[0]), "+f"(c[1]), "+f"(c[2]), "+f"(c[3])
                 : "r"(a0), "r"(a1), "r"(a2), "r"(a3), "r"(b0), "r"(b1));
}

// warp-tile m32 x n64 over K=128. A: smem [row][k] fp16 pitch PH. B: smem [n][k] fp16.
__device__ __forceinline__ void gemm_tile(const __half* As, const __half* Bs,
                                          int wr, int wc, int lane, float (*acc)[4]) {
    int r = lane >> 2, c = lane & 3;
#pragma unroll
    for (int ks = 0; ks < 8; ks++) {
        uint32_t a[2][4];
#pragma unroll
        for (int mi = 0; mi < 2; mi++) {
            const __half* Ap = As + (wr * 32 + mi * 16 + r) * PH + ks * 16 + 2 * c;
            a[mi][0] = *(const uint32_t*)(Ap);
            a[mi][1] = *(const uint32_t*)(Ap + 8 * PH);
            a[mi][2] = *(const uint32_t*)(Ap + 8);
            a[mi][3] = *(const uint32_t*)(Ap + 8 * PH + 8);
        }
#pragma unroll
        for (int ni = 0; ni < 8; ni++) {
            const __half* Bp = Bs + (wc * 64 + ni * 8 + r) * PH + ks * 16 + 2 * c;
            uint32_t b0 = *(const uint32_t*)(Bp);
            uint32_t b1 = *(const uint32_t*)(Bp + 8);
            mma16(acc[ni], a[0][0], a[0][1], a[0][2], a[0][3], b0, b1);
            mma16(acc[8 + ni], a[1][0], a[1][1], a[1][2], a[1][3], b0, b1);
        }
    }
}

__device__ __forceinline__ void stage_B(__half* Bs, const float* __restrict__ W, int t) {
    int j = t >> 1, k0 = (t & 1) * 64;
    const float* wr_ = W + j * D + k0;
    __half* bp = Bs + j * PH + k0;
#pragma unroll
    for (int k = 0; k < 64; k += 8) {
        float4 v0 = *(const float4*)(wr_ + k);
        float4 v1 = *(const float4*)(wr_ + k + 4);
        *(uint4*)(bp + k) = make_uint4(pk2(v0.x, v0.y), pk2(v0.z, v0.w),
                                       pk2(v1.x, v1.y), pk2(v1.z, v1.w));
    }
}

// ---------------- prep (+deg init) ----------------
__global__ void prep_kernel(const float* __restrict__ Wasrc, const float* __restrict__ Wadst,
                            const float* __restrict__ Wasub,
                            const float* __restrict__ basrc, const float* __restrict__ badst,
                            const float* __restrict__ basub, const float* __restrict__ bamul) {
    int i = blockIdx.x * blockDim.x + threadIdx.x;
    if (i < D * D) {
        g_WS[i] = Wasrc[i] + Wasub[i];
        g_WD[i] = Wadst[i] - Wasub[i];
    }
    if (i < D) g_be[i] = basrc[i] + badst[i] + basub[i] + bamul[i];
    if (i < NN) g_deg[i] = 0;
}

__global__ void deg_kernel(const int* __restrict__ dst) {
    int e = blockIdx.x * blockDim.x + threadIdx.x;
    if (e < NE) atomicAdd(&g_deg[dst[e]], 1);
}
__device__ __forceinline__ int block_incl_scan(int v, int t) {
    int lane = t & 31, w = t >> 5;
    int x = v;
#pragma unroll
    for (int o = 1; o < 32; o <<= 1) {
        int y = __shfl_up_sync(0xffffffffu, x, o);
        if (lane >= o) x += y;
    }
    __shared__ int ws[8];
    if (lane == 31) ws[w] = x;
    __syncthreads();
    if (t == 0) {
        int s = 0;
#pragma unroll
        for (int k = 0; k < 8; k++) { int tmp = ws[k]; ws[k] = s; s += tmp; }
    }
    __syncthreads();
    return x + ws[w];
}
__global__ void scan1_kernel() {
    int b = blockIdx.x, t = threadIdx.x, i = b * 256 + t;
    int v = (i < NN) ? g_deg[i] : 0;
    int x = block_incl_scan(v, t);
    if (i < NN) g_scantmp[i] = x;
    if (t == 255) g_bsum[b] = x;
}
// scan3 also derives its own block base from g_bsum (scan2 folded in)
__global__ void scan3_kernel() {
    int b = blockIdx.x, t = threadIdx.x, i = b * 256 + t;
    int v = (t < b && t < NBLK) ? g_bsum[t] : 0;
    int x = block_incl_scan(v, t);
    __shared__ int sbase;
    if (t == 255) sbase = x;
    __syncthreads();
    int base = sbase;
    if (i < NN) {
        int ex = g_scantmp[i] - g_deg[i] + base;
        g_rowptr[i] = ex;
        g_cursor[i] = ex;
        if (i == NN - 1) g_rowptr[NN] = ex + g_deg[i];
    }
}
__global__ void fill_kernel(const int* __restrict__ src, const int* __restrict__ dst) {
    int e = blockIdx.x * blockDim.x + threadIdx.x;
    if (e < NE) {
        int dn = dst[e];
        int p = atomicAdd(&g_cursor[dn], 1);
        g_sbuf[p] = src[e];
        g_dbuf[p] = dn;
    }
}

// ---------------- stage 1: node GEMMs (S, Dt, H, H2) + feat_h mirror ----------------
__global__ __launch_bounds__(256, 2) void node_mma(const float* __restrict__ feat,
                                                   const float* __restrict__ Wpool,
                                                   const float* __restrict__ bpool,
                                                   const float* __restrict__ Wpool2,
                                                   const float* __restrict__ bpool2) {
    extern __shared__ __half smh[];
    __half* As = smh;
    __half* Bs = smh + D * PH;
    __shared__ float sbias[D];
    int t = threadIdx.x, lane = t & 31, warp = t >> 5;
    int wr = warp >> 1, wc = warp & 1;
    int base = blockIdx.x * 128;

    {   // stage A = feat rows fp16; also mirror to g_feat_h
        int row = t >> 1, k0 = (t & 1) * 64;
        int node = base + row;
        __half* ap = As + row * PH + k0;
        if (node < NN) {
            const float* fr = feat + (size_t)node * D + k0;
            __half* gh = g_feat_h + (size_t)node * D + k0;
#pragma unroll
            for (int k = 0; k < 64; k += 8) {
                float4 v0 = *(const float4*)(fr + k);
                float4 v1 = *(const float4*)(fr + k + 4);
                uint4 u = make_uint4(pk2(v0.x, v0.y), pk2(v0.z, v0.w),
                                     pk2(v1.x, v1.y), pk2(v1.z, v1.w));
                *(uint4*)(ap + k) = u;
                *(uint4*)(gh + k) = u;
            }
        } else {
            for (int k = 0; k < 64; k += 8) *(uint4*)(ap + k) = make_uint4(0, 0, 0, 0);
        }
    }
    int r = lane >> 2, c = lane & 3;
    for (int mat = 0; mat < 4; mat++) {
        const float* W = mat == 0 ? g_WS : mat == 1 ? g_WD : mat == 2 ? Wpool : Wpool2;
        __syncthreads();
        stage_B(Bs, W, t);
        if (t < D) sbias[t] = (mat == 2) ? bpool[t] : (mat == 3) ? bpool2[t] : 0.f;
        __syncthreads();
        float acc[16][4];
#pragma unroll
        for (int i = 0; i < 16; i++)
#pragma unroll
            for (int q = 0; q < 4; q++) acc[i][q] = 0.f;
        gemm_tile(As, Bs, wr, wc, lane, acc);
        __half* OUT = mat == 0 ? g_S : mat == 1 ? g_Dt : mat == 2 ? g_H : g_H2;
#pragma unroll
        for (int mi = 0; mi < 2; mi++)
#pragma unroll
            for (int h = 0; h < 2; h++) {
                int node = base + wr * 32 + mi * 16 + r + h * 8;
                if (node < NN) {
#pragma unroll
                    for (int ni = 0; ni < 8; ni++) {
                        int col = wc * 64 + ni * 8 + 2 * c;
                        float v0 = acc[mi * 8 + ni][h * 2 + 0];
                        float v1 = acc[mi * 8 + ni][h * 2 + 1];
                        if (mat >= 2) {
                            v0 = gelu_f(v0 + sbias[col]);
                            v1 = gelu_f(v1 + sbias[col + 1]);
                        }
                        *(uint32_t*)(OUT + (size_t)node * D + col) = pk2(v0, v1);
                    }
                }
            }
    }
}

// ---------------- stage 2: edge scores (CSR order, 5 tiles/block, B staged once) ----
__global__ __launch_bounds__(256, 2) void edge_mma(const float* __restrict__ waout,
                                                   const float* __restrict__ baout,
                                                   const float* __restrict__ Wamul) {
    extern __shared__ __half smh[];
    __half* As = smh;
    __half* Bs = smh + D * PH;
    float* red = (float*)(smh + 2 * D * PH);   // [128][8]
    __shared__ int ssrc[128], sdst_[128];
    __shared__ float sbias[D], sw[D];
    int t = threadIdx.x, lane = t & 31, warp = t >> 5;
    int wr = warp >> 1, wc = warp & 1;
    int r = lane >> 2, c = lane & 3;
    int p0 = blockIdx.x * 128 * ETILES;
    float bao = baout[0];

    stage_B(Bs, Wamul, t);
    if (t < D) { sbias[t] = g_be[t]; sw[t] = waout[t]; }

    for (int et = 0; et < ETILES; et++, p0 += 128) {
        __syncthreads();
        if (t < 128) {
            ssrc[t] = g_sbuf[p0 + t];
            sdst_[t] = g_dbuf[p0 + t];
        }
        __syncthreads();
        {   // stage A = fs*fd from fp16 mirror
            int row = t >> 1, k0 = (t & 1) * 64;
            const __half* rs = g_feat_h + (size_t)ssrc[row] * D + k0;
            const __half* rd = g_feat_h + (size_t)sdst_[row] * D + k0;
            __half* ap = As + row * PH + k0;
#pragma unroll
            for (int k = 0; k < 64; k += 8) {
                uint4 ua = *(const uint4*)(rs + k);
                uint4 ub = *(const uint4*)(rd + k);
                float2 a0 = up2(ua.x), a1 = up2(ua.y), a2 = up2(ua.z), a3 = up2(ua.w);
                float2 b0 = up2(ub.x), b1 = up2(ub.y), b2 = up2(ub.z), b3 = up2(ub.w);
                *(uint4*)(ap + k) = make_uint4(pk2(a0.x * b0.x, a0.y * b0.y),
                                               pk2(a1.x * b1.x, a1.y * b1.y),
                                               pk2(a2.x * b2.x, a2.y * b2.y),
                                               pk2(a3.x * b3.x, a3.y * b3.y));
            }
        }
        __syncthreads();
        float acc[16][4];
#pragma unroll
        for (int i = 0; i < 16; i++)
#pragma unroll
            for (int q = 0; q < 4; q++) acc[i][q] = 0.f;
        gemm_tile(As, Bs, wr, wc, lane, acc);

#pragma unroll
        for (int mi = 0; mi < 2; mi++)
#pragma unroll
            for (int h = 0; h < 2; h++) {
                int row = wr * 32 + mi * 16 + r + h * 8;
                int sn = ssrc[row], dn = sdst_[row];
                float p = 0.f;
#pragma unroll
                for (int ni = 0; ni < 8; ni++) {
                    int col = wc * 64 + ni * 8 + 2 * c;
                    float2 s2 = up2(*(const uint32_t*)(g_S + (size_t)sn * D + col));
                    float2 d2 = up2(*(const uint32_t*)(g_Dt + (size_t)dn * D + col));
                    float v0 = acc[mi * 8 + ni][h * 2 + 0] + s2.x + d2.x + sbias[col];
                    float v1 = acc[mi * 8 + ni][h * 2 + 1] + s2.y + d2.y + sbias[col + 1];
                    p = fmaf(gelu_f(v0), sw[col], p);
                    p = fmaf(gelu_f(v1), sw[col + 1], p);
                }
                red[row * 8 + wc * 4 + c] = p;
            }
        __syncthreads();
        if (t < 128) {
            float s = 0.f;
#pragma unroll
            for (int x = 0; x < 8; x++) s += red[t * 8 + x];
            s += bao;
            s = (s > 0.f) ? s : 0.2f * s;
            g_score[p0 + t] = s;
        }
    }
}

// ---------------- stage 3: aggregation (warp per node, unroll 4) ----------------
__global__ void agg_kernel() {
    int gw = (blockIdx.x * blockDim.x + threadIdx.x) >> 5;
    int lane = threadIdx.x & 31;
    if (gw >= NN) return;
    int beg = g_rowptr[gw], end = g_rowptr[gw + 1];
    int off = lane * 4;
    float4 mx = make_float4(-FLT_MAX, -FLT_MAX, -FLT_MAX, -FLT_MAX);
    float4 sum = make_float4(0.f, 0.f, 0.f, 0.f);
    int p = beg;
    for (; p + 3 < end; p += 4) {
        float sc0 = g_score[p], sc1 = g_score[p + 1];
        float sc2 = g_score[p + 2], sc3 = g_score[p + 3];
        int sn0 = g_sbuf[p], sn1 = g_sbuf[p + 1];
        int sn2 = g_sbuf[p + 2], sn3 = g_sbuf[p + 3];
        uint2 uh0 = *(const uint2*)(g_H + (size_t)sn0 * D + off);
        uint2 uh1 = *(const uint2*)(g_H + (size_t)sn1 * D + off);
        uint2 uh2 = *(const uint2*)(g_H + (size_t)sn2 * D + off);
        uint2 uh3 = *(const uint2*)(g_H + (size_t)sn3 * D + off);
        uint2 ug0 = *(const uint2*)(g_H2 + (size_t)sn0 * D + off);
        uint2 ug1 = *(const uint2*)(g_H2 + (size_t)sn1 * D + off);
        uint2 ug2 = *(const uint2*)(g_H2 + (size_t)sn2 * D + off);
        uint2 ug3 = *(const uint2*)(g_H2 + (size_t)sn3 * D + off);
        float2 a, b;
        a = up2(uh0.x); b = up2(uh0.y);
        mx.x = fmaxf(mx.x, sc0 * a.x); mx.y = fmaxf(mx.y, sc0 * a.y);
        mx.z = fmaxf(mx.z, sc0 * b.x); mx.w = fmaxf(mx.w, sc0 * b.y);
        a = up2(uh1.x); b = up2(uh1.y);
        mx.x = fmaxf(mx.x, sc1 * a.x); mx.y = fmaxf(mx.y, sc1 * a.y);
        mx.z = fmaxf(mx.z, sc1 * b.x); mx.w = fmaxf(mx.w, sc1 * b.y);
        a = up2(uh2.x); b = up2(uh2.y);
        mx.x = fmaxf(mx.x, sc2 * a.x); mx.y = fmaxf(mx.y, sc2 * a.y);
        mx.z = fmaxf(mx.z, sc2 * b.x); mx.w = fmaxf(mx.w, sc2 * b.y);
        a = up2(uh3.x); b = up2(uh3.y);
        mx.x = fmaxf(mx.x, sc3 * a.x); mx.y = fmaxf(mx.y, sc3 * a.y);
        mx.z = fmaxf(mx.z, sc3 * b.x); mx.w = fmaxf(mx.w, sc3 * b.y);
        a = up2(ug0.x); b = up2(ug0.y);
        sum.x = fmaf(sc0, a.x, sum.x); sum.y = fmaf(sc0, a.y, sum.y);
        sum.z = fmaf(sc0, b.x, sum.z); sum.w = fmaf(sc0, b.y, sum.w);
        a = up2(ug1.x); b = up2(ug1.y);
        sum.x = fmaf(sc1, a.x, sum.x); sum.y = fmaf(sc1, a.y, sum.y);
        sum.z = fmaf(sc1, b.x, sum.z); sum.w = fmaf(sc1, b.y, sum.w);
        a = up2(ug2.x); b = up2(ug2.y);
        sum.x = fmaf(sc2, a.x, sum.x); sum.y = fmaf(sc2, a.y, sum.y);
        sum.z = fmaf(sc2, b.x, sum.z); sum.w = fmaf(sc2, b.y, sum.w);
        a = up2(ug3.x); b = up2(ug3.y);
        sum.x = fmaf(sc3, a.x, sum.x); sum.y = fmaf(sc3, a.y, sum.y);
        sum.z = fmaf(sc3, b.x, sum.z); sum.w = fmaf(sc3, b.y, sum.w);
    }
    for (; p < end; p++) {
        float sc = g_score[p];
        int sn = g_sbuf[p];
        uint2 uh = *(const uint2*)(g_H + (size_t)sn * D + off);
        uint2 ug = *(const uint2*)(g_H2 + (size_t)sn * D + off);
        float2 h0 = up2(uh.x), h1 = up2(uh.y);
        float2 g0 = up2(ug.x), g1 = up2(ug.y);
        mx.x = fmaxf(mx.x, sc * h0.x); mx.y = fmaxf(mx.y, sc * h0.y);
        mx.z = fmaxf(mx.z, sc * h1.x); mx.w = fmaxf(mx.w, sc * h1.y);
        sum.x = fmaf(sc, g0.x, sum.x); sum.y = fmaf(sc, g0.y, sum.y);
        sum.z = fmaf(sc, g1.x, sum.z); sum.w = fmaf(sc, g1.y, sum.w);
    }
    int d = end - beg;
    if (d == 0) mx = make_float4(0.f, 0.f, 0.f, 0.f);
    float inv = 1.f / (float)(d > 1 ? d : 1);
    *(uint2*)(g_neigh + (size_t)gw * D + off) =
        make_uint2(pk2(mx.x, mx.y), pk2(mx.z, mx.w));
    *(uint2*)(g_neigh2 + (size_t)gw * D + off) =
        make_uint2(pk2(sum.x * inv, sum.y * inv), pk2(sum.z * inv, sum.w * inv));
}

// ---------------- stage 4: output GEMMs + fused MLP (in-place accumulate) ------
__global__ __launch_bounds__(256, 2) void final_mma(const float* __restrict__ feat,
                                                    const float* __restrict__ Wself,
                                                    const float* __restrict__ bself,
                                                    const float* __restrict__ Wneigh,
                                                    const float* __restrict__ bneigh,
                                                    const float* __restrict__ Wneigh2,
                                                    const float* __restrict__ bneigh2,
                                                    const float* __restrict__ Wmlp,
                                                    const float* __restrict__ bmlp,
                                                    float* __restrict__ out) {
    extern __shared__ __half smh[];
    __half* As = smh;
    __half* Bs = smh + D * PH;
    __shared__ float sbias[D], sb2[D];
    int t = threadIdx.x, lane = t & 31, warp = t >> 5;
    int wr = warp >> 1, wc = warp & 1;
    int base = blockIdx.x * 128;
    int r = lane >> 2, c = lane & 3;

    if (t < D) sbias[t] = bself[t] + bneigh[t] + bneigh2[t];
    float acc[16][4];
#pragma unroll
    for (int i = 0; i < 16; i++)
#pragma unroll
        for (int q = 0; q < 4; q++) acc[i][q] = 0.f;

    for (int s3 = 0; s3 < 3; s3++) {
        const float* W = s3 == 0 ? Wself : s3 == 1 ? Wneigh : Wneigh2;
        __syncthreads();
        {
            int row = t >> 1, k0 = (t & 1) * 64;
            int node = base + row;
            __half* ap = As + row * PH + k0;
            if (node >= NN) {
                for (int k = 0; k < 64; k += 8) *(uint4*)(ap + k) = make_uint4(0, 0, 0, 0);
            } else if (s3 == 0) {
                const float* fr = feat + (size_t)node * D + k0;
#pragma unroll
                for (int k = 0; k < 64; k += 8) {
                    float4 v0 = *(const float4*)(fr + k);
                    float4 v1 = *(const float4*)(fr + k + 4);
                    *(uint4*)(ap + k) = make_uint4(pk2(v0.x, v0.y), pk2(v0.z, v0.w),
                                                   pk2(v1.x, v1.y), pk2(v1.z, v1.w));
                }
            } else {
                const __half* Xh = (s3 == 1 ? g_neigh : g_neigh2) + (size_t)node * D + k0;
#pragma unroll
                for (int k = 0; k < 64; k += 8)
                    *(uint4*)(ap + k) = *(const uint4*)(Xh + k);
            }
        }
        stage_B(Bs, W, t);
        __syncthreads();
        gemm_tile(As, Bs, wr, wc, lane, acc);
    }
#pragma unroll
    for (int mi = 0; mi < 2; mi++)
#pragma unroll
        for (int ni = 0; ni < 8; ni++) {
            int col = wc * 64 + ni * 8 + 2 * c;
            acc[mi * 8 + ni][0] += sbias[col];
            acc[mi * 8 + ni][1] += sbias[col + 1];
            acc[mi * 8 + ni][2] += sbias[col];
            acc[mi * 8 + ni][3] += sbias[col + 1];
        }

    for (int li = 0; li < 2; li++) {
        __syncthreads();
#pragma unroll
        for (int mi = 0; mi < 2; mi++)
#pragma unroll
            for (int h = 0; h < 2; h++) {
                int row = wr * 32 + mi * 16 + r + h * 8;
#pragma unroll
                for (int ni = 0; ni < 8; ni++) {
                    int col = wc * 64 + ni * 8 + 2 * c;
                    *(uint32_t*)(As + row * PH + col) =
                        pk2(gelu_f(acc[mi * 8 + ni][h * 2 + 0]),
                            gelu_f(acc[mi * 8 + ni][h * 2 + 1]));
                }
            }
        stage_B(Bs, Wmlp + (size_t)li * D * D, t);
        if (t < D) sb2[t] = bmlp[li * D + t];
        __syncthreads();
        gemm_tile(As, Bs, wr, wc, lane, acc);   // acc += gelu(rst) @ W^T  (in place)
#pragma unroll
        for (int mi = 0; mi < 2; mi++)
#pragma unroll
            for (int ni = 0; ni < 8; ni++) {
                int col = wc * 64 + ni * 8 + 2 * c;
                acc[mi * 8 + ni][0] += sb2[col];
                acc[mi * 8 + ni][1] += sb2[col + 1];
                acc[mi * 8 + ni][2] += sb2[col];
                acc[mi * 8 + ni][3] += sb2[col + 1];
            }
    }
#pragma unroll
    for (int mi = 0; mi < 2; mi++)
#pragma unroll
        for (int h = 0; h < 2; h++) {
            int node = base + wr * 32 + mi * 16 + r + h * 8;
            if (node < NN) {
#pragma unroll
                for (int ni = 0; ni < 8; ni++) {
                    int col = wc * 64 + ni * 8 + 2 * c;
                    *(float2*)(out + (size_t)node * D + col) =
                        make_float2(acc[mi * 8 + ni][h * 2 + 0], acc[mi * 8 + ni][h * 2 + 1]);
                }
            }
        }
}

// ---------------- launch (forked graph: CSR build || node GEMMs) ----------------
extern "C" void kernel_launch(void* const* d_in, const int* in_sizes, int n_in,
                              void* d_out, int out_size) {
    const float* feat = (const float*)d_in[0];
    const int* src = (const int*)d_in[1];
    const int* dst = (const int*)d_in[2];
    const float* Wasrc = (const float*)d_in[3];
    const float* basrc = (const float*)d_in[4];
    const float* Wadst = (const float*)d_in[5];
    const float* badst = (const float*)d_in[6];
    const float* Wasub = (const float*)d_in[7];
    const float* basub = (const float*)d_in[8];
    const float* Wamul = (const float*)d_in[9];
    const float* bamul = (const float*)d_in[10];
    const float* Waout = (const float*)d_in[11];
    const float* baout = (const float*)d_in[12];
    const float* Wpool = (const float*)d_in[13];
    const float* bpool = (const float*)d_in[14];
    const float* Wpool2 = (const float*)d_in[15];
    const float* bpool2 = (const float*)d_in[16];
    const float* Wself = (const float*)d_in[17];
    const float* bself = (const float*)d_in[18];
    const float* Wneigh = (const float*)d_in[19];
    const float* bneigh = (const float*)d_in[20];
    const float* Wneigh2 = (const float*)d_in[21];
    const float* bneigh2 = (const float*)d_in[22];
    const float* Wmlp = (const float*)d_in[23];
    const float* bmlp = (const float*)d_in[24];
    float* out = (float*)d_out;

    static cudaStream_t s1 = nullptr;
    static cudaEvent_t evFork = nullptr, evJoin = nullptr;
    if (s1 == nullptr) {
        cudaStreamCreateWithFlags(&s1, cudaStreamNonBlocking);
        cudaEventCreateWithFlags(&evFork, cudaEventDisableTiming);
        cudaEventCreateWithFlags(&evJoin, cudaEventDisableTiming);
    }

    const int SMEM_AB = 2 * D * PH * (int)sizeof(__half);          // 69632
    const int SMEM_EDGE = SMEM_AB + 128 * 8 * (int)sizeof(float);  // 73728
    cudaFuncSetAttribute(node_mma, cudaFuncAttributeMaxDynamicSharedMemorySize, SMEM_AB);
    cudaFuncSetAttribute(edge_mma, cudaFuncAttributeMaxDynamicSharedMemorySize, SMEM_EDGE);
    cudaFuncSetAttribute(final_mma, cudaFuncAttributeMaxDynamicSharedMemorySize, SMEM_AB);

    prep_kernel<<<NBLK, 256>>>(Wasrc, Wadst, Wasub, basrc, badst, basub, bamul);

    cudaEventRecord(evFork, 0);
    cudaStreamWaitEvent(s1, evFork, 0);
    node_mma<<<(NN + 127) / 128, 256, SMEM_AB, s1>>>(feat, Wpool, bpool, Wpool2, bpool2);
    cudaEventRecord(evJoin, s1);

    deg_kernel<<<(NE + 255) / 256, 256>>>(dst);
    scan1_kernel<<<NBLK, 256>>>();
    scan3_kernel<<<NBLK, 256>>>();
    fill_kernel<<<(NE + 255) / 256, 256>>>(src, dst);

    cudaStreamWaitEvent(0, evJoin, 0);
    edge_mma<<<NE / (128 * ETILES), 256, SMEM_EDGE>>>(Waout, baout, Wamul);
    agg_kernel<<<(NN * 32 + 255) / 256, 256>>>();
    final_mma<<<(NN + 127) / 128, 256, SMEM_AB>>>(feat, Wself, bself, Wneigh, bneigh,
                                                  Wneigh2, bneigh2, Wmlp, bmlp, out);
}

// round 14
// speedup vs baseline: 1.6150x; 1.6150x over previous
#include <cuda_runtime.h>
#include <cuda_fp16.h>
#include <cstdint>
#include <math.h>
#include <float.h>

#define NN 50000
#define NE 800000
#define D 128
#define PH 136            // smem pitch in halves
#define NBLK 196

__device__ __half g_feat_h[NN * D];
__device__ __half g_S[NN * D];
__device__ __half g_Dt[NN * D];
__device__ __half g_H[NN * D];
__device__ __half g_H2[NN * D];
__device__ __half g_neigh[NN * D];
__device__ __half g_neigh2[NN * D];
__device__ int   g_deg[NN];
__device__ int   g_rowptr[NN + 1];
__device__ int   g_cursor[NN];
__device__ int   g_scantmp[NN];
__device__ int   g_bsum[256];
__device__ int   g_bbase[256];
__device__ int   g_sbuf[NE];
__device__ int   g_dbuf[NE];
__device__ float g_score[NE];
__device__ float g_be[D];
// fp16 pre-converted weights (staged to smem as pure copies)
__device__ __half g_WSh[D * D];
__device__ __half g_WDh[D * D];
__device__ __half g_Wamulh[D * D];
__device__ __half g_Wpoolh[D * D];
__device__ __half g_Wpool2h[D * D];
__device__ __half g_Wselfh[D * D];
__device__ __half g_Wneighh[D * D];
__device__ __half g_Wneigh2h[D * D];
__device__ __half g_Wmlph[2 * D * D];

__device__ __forceinline__ float gelu_f(float x) {
    return 0.5f * x * (1.0f + erff(x * 0.70710678118654752f));
}
__device__ __forceinline__ uint32_t pk2(float x, float y) {
    __half2 h = __floats2half2_rn(x, y);
    return *(uint32_t*)&h;
}
__device__ __forceinline__ float2 up2(uint32_t u) {
    return __half22float2(*(__half2*)&u);
}
__device__ __forceinline__ void mma16(float* c, uint32_t a0, uint32_t a1, uint32_t a2,
                                      uint32_t a3, uint32_t b0, uint32_t b1) {
    asm volatile("mma.sync.aligned.m16n8k16.row.col.f32.f16.f16.f32 "
                 "{%0,%1,%2,%3},{%4,%5,%6,%7},{%8,%9},{%0,%1,%2,%3};"
                 : "+f"(c[0]), "+f"(c[1]), "+f"(c[2]), "+f"(c[3])
                 : "r"(a0), "r"(a1), "r"(a2), "r"(a3), "r"(b0), "r"(b1));
}

// warp-tile m32 x n64 over K=128. A: smem [row][k] fp16 pitch PH. B: smem [n][k] fp16.
__device__ __forceinline__ void gemm_tile(const __half* As, const __half* Bs,
                                          int wr, int wc, int lane, float (*acc)[4]) {
    int r = lane >> 2, c = lane & 3;
#pragma unroll
    for (int ks = 0; ks < 8; ks++) {
        uint32_t a[2][4];
#pragma unroll
        for (int mi = 0; mi < 2; mi++) {
            const __half* Ap = As + (wr * 32 + mi * 16 + r) * PH + ks * 16 + 2 * c;
            a[mi][0] = *(const uint32_t*)(Ap);
            a[mi][1] = *(const uint32_t*)(Ap + 8 * PH);
            a[mi][2] = *(const uint32_t*)(Ap + 8);
            a[mi][3] = *(const uint32_t*)(Ap + 8 * PH + 8);
        }
#pragma unroll
        for (int ni = 0; ni < 8; ni++) {
            const __half* Bp = Bs + (wc * 64 + ni * 8 + r) * PH + ks * 16 + 2 * c;
            uint32_t b0 = *(const uint32_t*)(Bp);
            uint32_t b1 = *(const uint32_t*)(Bp + 8);
            mma16(acc[ni], a[0][0], a[0][1], a[0][2], a[0][3], b0, b1);
            mma16(acc[8 + ni], a[1][0], a[1][1], a[1][2], a[1][3], b0, b1);
        }
    }
}

// stage pre-converted fp16 weight [D][D] -> smem tile (pure copy, 256 threads)
__device__ __forceinline__ void stage_Bh(__half* Bs, const __half* __restrict__ Wh, int t) {
    int j = t >> 1, k0 = (t & 1) * 64;
    const __half* wr_ = Wh + j * D + k0;
    __half* bp = Bs + j * PH + k0;
#pragma unroll
    for (int k = 0; k < 64; k += 8)
        *(uint4*)(bp + k) = *(const uint4*)(wr_ + k);
}

// ---------------- prep (+deg init + fp16 weight conversion) ----------------
__global__ void prep_kernel(const float* __restrict__ Wasrc, const float* __restrict__ Wadst,
                            const float* __restrict__ Wasub, const float* __restrict__ Wamul,
                            const float* __restrict__ Wpool, const float* __restrict__ Wpool2,
                            const float* __restrict__ Wself, const float* __restrict__ Wneigh,
                            const float* __restrict__ Wneigh2, const float* __restrict__ Wmlp,
                            const float* __restrict__ basrc, const float* __restrict__ badst,
                            const float* __restrict__ basub, const float* __restrict__ bamul) {
    int i = blockIdx.x * blockDim.x + threadIdx.x;
    if (i < D * D) {
        g_WSh[i] = __float2half_rn(Wasrc[i] + Wasub[i]);
        g_WDh[i] = __float2half_rn(Wadst[i] - Wasub[i]);
        g_Wamulh[i] = __float2half_rn(Wamul[i]);
        g_Wpoolh[i] = __float2half_rn(Wpool[i]);
        g_Wpool2h[i] = __float2half_rn(Wpool2[i]);
        g_Wselfh[i] = __float2half_rn(Wself[i]);
        g_Wneighh[i] = __float2half_rn(Wneigh[i]);
        g_Wneigh2h[i] = __float2half_rn(Wneigh2[i]);
        g_Wmlph[i] = __float2half_rn(Wmlp[i]);
        g_Wmlph[D * D + i] = __float2half_rn(Wmlp[D * D + i]);
    }
    if (i < D) g_be[i] = basrc[i] + badst[i] + basub[i] + bamul[i];
    if (i < NN) g_deg[i] = 0;
}

__global__ void deg_kernel(const int* __restrict__ dst) {
    int e = blockIdx.x * blockDim.x + threadIdx.x;
    if (e < NE) atomicAdd(&g_deg[dst[e]], 1);
}
__device__ __forceinline__ int block_incl_scan(int v, int t) {
    int lane = t & 31, w = t >> 5;
    int x = v;
#pragma unroll
    for (int o = 1; o < 32; o <<= 1) {
        int y = __shfl_up_sync(0xffffffffu, x, o);
        if (lane >= o) x += y;
    }
    __shared__ int ws[8];
    if (lane == 31) ws[w] = x;
    __syncthreads();
    if (t == 0) {
        int s = 0;
#pragma unroll
        for (int k = 0; k < 8; k++) { int tmp = ws[k]; ws[k] = s; s += tmp; }
    }
    __syncthreads();
    return x + ws[w];
}
__global__ void scan1_kernel() {
    int b = blockIdx.x, t = threadIdx.x, i = b * 256 + t;
    int v = (i < NN) ? g_deg[i] : 0;
    int x = block_incl_scan(v, t);
    if (i < NN) g_scantmp[i] = x;
    if (t == 255) g_bsum[b] = x;
}
__global__ void scan2_kernel() {
    int t = threadIdx.x;
    int v = (t < NBLK) ? g_bsum[t] : 0;
    int x = block_incl_scan(v, t);
    g_bbase[t] = x - v;
}
__global__ void scan3_kernel() {
    int b = blockIdx.x, t = threadIdx.x, i = b * 256 + t;
    if (i < NN) {
        int ex = g_scantmp[i] - g_deg[i] + g_bbase[b];
        g_rowptr[i] = ex;
        g_cursor[i] = ex;
        if (i == NN - 1) g_rowptr[NN] = ex + g_deg[i];
    }
}
__global__ void fill_kernel(const int* __restrict__ src, const int* __restrict__ dst) {
    int e = blockIdx.x * blockDim.x + threadIdx.x;
    if (e < NE) {
        int dn = dst[e];
        int p = atomicAdd(&g_cursor[dn], 1);
        g_sbuf[p] = src[e];
        g_dbuf[p] = dn;
    }
}

// ---------------- stage 1: node GEMMs (S, Dt, H, H2) + feat_h mirror ----------------
__global__ __launch_bounds__(256, 2) void node_mma(const float* __restrict__ feat,
                                                   const float* __restrict__ bpool,
                                                   const float* __restrict__ bpool2) {
    extern __shared__ __half smh[];
    __half* As = smh;
    __half* Bs = smh + D * PH;
    __shared__ float sbias[D];
    int t = threadIdx.x, lane = t & 31, warp = t >> 5;
    int wr = warp >> 1, wc = warp & 1;
    int base = blockIdx.x * 128;

    {   // stage A = feat rows fp16; also mirror to g_feat_h
        int row = t >> 1, k0 = (t & 1) * 64;
        int node = base + row;
        __half* ap = As + row * PH + k0;
        if (node < NN) {
            const float* fr = feat + (size_t)node * D + k0;
            __half* gh = g_feat_h + (size_t)node * D + k0;
#pragma unroll
            for (int k = 0; k < 64; k += 8) {
                float4 v0 = *(const float4*)(fr + k);
                float4 v1 = *(const float4*)(fr + k + 4);
                uint4 u = make_uint4(pk2(v0.x, v0.y), pk2(v0.z, v0.w),
                                     pk2(v1.x, v1.y), pk2(v1.z, v1.w));
                *(uint4*)(ap + k) = u;
                *(uint4*)(gh + k) = u;
            }
        } else {
            for (int k = 0; k < 64; k += 8) *(uint4*)(ap + k) = make_uint4(0, 0, 0, 0);
        }
    }
    int r = lane >> 2, c = lane & 3;
    for (int mat = 0; mat < 4; mat++) {
        const __half* W = mat == 0 ? g_WSh : mat == 1 ? g_WDh : mat == 2 ? g_Wpoolh : g_Wpool2h;
        __syncthreads();
        stage_Bh(Bs, W, t);
        if (t < D) sbias[t] = (mat == 2) ? bpool[t] : (mat == 3) ? bpool2[t] : 0.f;
        __syncthreads();
        float acc[16][4];
#pragma unroll
        for (int i = 0; i < 16; i++)
#pragma unroll
            for (int q = 0; q < 4; q++) acc[i][q] = 0.f;
        gemm_tile(As, Bs, wr, wc, lane, acc);
        __half* OUT = mat == 0 ? g_S : mat == 1 ? g_Dt : mat == 2 ? g_H : g_H2;
#pragma unroll
        for (int mi = 0; mi < 2; mi++)
#pragma unroll
            for (int h = 0; h < 2; h++) {
                int node = base + wr * 32 + mi * 16 + r + h * 8;
                if (node < NN) {
#pragma unroll
                    for (int ni = 0; ni < 8; ni++) {
                        int col = wc * 64 + ni * 8 + 2 * c;
                        float v0 = acc[mi * 8 + ni][h * 2 + 0];
                        float v1 = acc[mi * 8 + ni][h * 2 + 1];
                        if (mat >= 2) {
                            v0 = gelu_f(v0 + sbias[col]);
                            v1 = gelu_f(v1 + sbias[col + 1]);
                        }
                        *(uint32_t*)(OUT + (size_t)node * D + col) = pk2(v0, v1);
                    }
                }
            }
    }
}

// ---------------- stage 2: edge scores (CSR order, fp16 gathers) ----------------
__global__ __launch_bounds__(256, 2) void edge_mma(const float* __restrict__ waout,
                                                   const float* __restrict__ baout) {
    extern __shared__ __half smh[];
    __half* As = smh;
    __half* Bs = smh + D * PH;
    float* red = (float*)(smh + 2 * D * PH);   // [128][8]
    __shared__ int ssrc[128], sdst_[128];
    __shared__ float sbias[D], sw[D];
    int t = threadIdx.x, lane = t & 31, warp = t >> 5;
    int wr = warp >> 1, wc = warp & 1;
    int p0 = blockIdx.x * 128;

    if (t < 128) {
        ssrc[t] = g_sbuf[p0 + t];
        sdst_[t] = g_dbuf[p0 + t];
        sbias[t] = g_be[t];
        sw[t] = waout[t];
    }
    stage_Bh(Bs, g_Wamulh, t);
    __syncthreads();
    {   // stage A = fs*fd from fp16 mirror
        int row = t >> 1, k0 = (t & 1) * 64;
        const __half* rs = g_feat_h + (size_t)ssrc[row] * D + k0;
        const __half* rd = g_feat_h + (size_t)sdst_[row] * D + k0;
        __half* ap = As + row * PH + k0;
#pragma unroll
        for (int k = 0; k < 64; k += 8) {
            uint4 ua = *(const uint4*)(rs + k);
            uint4 ub = *(const uint4*)(rd + k);
            float2 a0 = up2(ua.x), a1 = up2(ua.y), a2 = up2(ua.z), a3 = up2(ua.w);
            float2 b0 = up2(ub.x), b1 = up2(ub.y), b2 = up2(ub.z), b3 = up2(ub.w);
            *(uint4*)(ap + k) = make_uint4(pk2(a0.x * b0.x, a0.y * b0.y),
                                           pk2(a1.x * b1.x, a1.y * b1.y),
                                           pk2(a2.x * b2.x, a2.y * b2.y),
                                           pk2(a3.x * b3.x, a3.y * b3.y));
        }
    }
    __syncthreads();
    float acc[16][4];
#pragma unroll
    for (int i = 0; i < 16; i++)
#pragma unroll
        for (int q = 0; q < 4; q++) acc[i][q] = 0.f;
    gemm_tile(As, Bs, wr, wc, lane, acc);

    int r = lane >> 2, c = lane & 3;
#pragma unroll
    for (int mi = 0; mi < 2; mi++)
#pragma unroll
        for (int h = 0; h < 2; h++) {
            int row = wr * 32 + mi * 16 + r + h * 8;
            int sn = ssrc[row], dn = sdst_[row];
            float p = 0.f;
#pragma unroll
            for (int ni = 0; ni < 8; ni++) {
                int col = wc * 64 + ni * 8 + 2 * c;
                float2 s2 = up2(*(const uint32_t*)(g_S + (size_t)sn * D + col));
                float2 d2 = up2(*(const uint32_t*)(g_Dt + (size_t)dn * D + col));
                float v0 = acc[mi * 8 + ni][h * 2 + 0] + s2.x + d2.x + sbias[col];
                float v1 = acc[mi * 8 + ni][h * 2 + 1] + s2.y + d2.y + sbias[col + 1];
                p = fmaf(gelu_f(v0), sw[col], p);
                p = fmaf(gelu_f(v1), sw[col + 1], p);
            }
            red[row * 8 + wc * 4 + c] = p;
        }
    __syncthreads();
    if (t < 128) {
        float s = 0.f;
#pragma unroll
        for (int x = 0; x < 8; x++) s += red[t * 8 + x];
        s += baout[0];
        s = (s > 0.f) ? s : 0.2f * s;
        g_score[p0 + t] = s;
    }
}

// ---------------- stage 3: aggregation (warp per node, unroll 2) ----------------
__global__ void agg_kernel() {
    int gw = (blockIdx.x * blockDim.x + threadIdx.x) >> 5;
    int lane = threadIdx.x & 31;
    if (gw >= NN) return;
    int beg = g_rowptr[gw], end = g_rowptr[gw + 1];
    int off = lane * 4;
    float4 mx = make_float4(-FLT_MAX, -FLT_MAX, -FLT_MAX, -FLT_MAX);
    float4 sum = make_float4(0.f, 0.f, 0.f, 0.f);
    int p = beg;
    for (; p + 1 < end; p += 2) {
        float sc0 = g_score[p], sc1 = g_score[p + 1];
        int sn0 = g_sbuf[p], sn1 = g_sbuf[p + 1];
        uint2 uha = *(const uint2*)(g_H + (size_t)sn0 * D + off);
        uint2 uhb = *(const uint2*)(g_H + (size_t)sn1 * D + off);
        uint2 uga = *(const uint2*)(g_H2 + (size_t)sn0 * D + off);
        uint2 ugb = *(const uint2*)(g_H2 + (size_t)sn1 * D + off);
        float2 ha0 = up2(uha.x), ha1 = up2(uha.y);
        float2 hb0 = up2(uhb.x), hb1 = up2(uhb.y);
        float2 ga0 = up2(uga.x), ga1 = up2(uga.y);
        float2 gb0 = up2(ugb.x), gb1 = up2(ugb.y);
        mx.x = fmaxf(mx.x, fmaxf(sc0 * ha0.x, sc1 * hb0.x));
        mx.y = fmaxf(mx.y, fmaxf(sc0 * ha0.y, sc1 * hb0.y));
        mx.z = fmaxf(mx.z, fmaxf(sc0 * ha1.x, sc1 * hb1.x));
        mx.w = fmaxf(mx.w, fmaxf(sc0 * ha1.y, sc1 * hb1.y));
        sum.x = fmaf(sc1, gb0.x, fmaf(sc0, ga0.x, sum.x));
        sum.y = fmaf(sc1, gb0.y, fmaf(sc0, ga0.y, sum.y));
        sum.z = fmaf(sc1, gb1.x, fmaf(sc0, ga1.x, sum.z));
        sum.w = fmaf(sc1, gb1.y, fmaf(sc0, ga1.y, sum.w));
    }
    if (p < end) {
        float sc = g_score[p];
        int sn = g_sbuf[p];
        uint2 uh = *(const uint2*)(g_H + (size_t)sn * D + off);
        uint2 ug = *(const uint2*)(g_H2 + (size_t)sn * D + off);
        float2 h0 = up2(uh.x), h1 = up2(uh.y);
        float2 g0 = up2(ug.x), g1 = up2(ug.y);
        mx.x = fmaxf(mx.x, sc * h0.x); mx.y = fmaxf(mx.y, sc * h0.y);
        mx.z = fmaxf(mx.z, sc * h1.x); mx.w = fmaxf(mx.w, sc * h1.y);
        sum.x = fmaf(sc, g0.x, sum.x); sum.y = fmaf(sc, g0.y, sum.y);
        sum.z = fmaf(sc, g1.x, sum.z); sum.w = fmaf(sc, g1.y, sum.w);
    }
    int d = end - beg;
    if (d == 0) mx = make_float4(0.f, 0.f, 0.f, 0.f);
    float inv = 1.f / (float)(d > 1 ? d : 1);
    *(uint2*)(g_neigh + (size_t)gw * D + off) =
        make_uint2(pk2(mx.x, mx.y), pk2(mx.z, mx.w));
    *(uint2*)(g_neigh2 + (size_t)gw * D + off) =
        make_uint2(pk2(sum.x * inv, sum.y * inv), pk2(sum.z * inv, sum.w * inv));
}

// ---------------- stage 4: output GEMMs + fused MLP (in-place accumulate) ------
__global__ __launch_bounds__(256, 2) void final_mma(const float* __restrict__ feat,
                                                    const float* __restrict__ bself,
                                                    const float* __restrict__ bneigh,
                                                    const float* __restrict__ bneigh2,
                                                    const float* __restrict__ bmlp,
                                                    float* __restrict__ out) {
    extern __shared__ __half smh[];
    __half* As = smh;
    __half* Bs = smh + D * PH;
    __shared__ float sbias[D], sb2[D];
    int t = threadIdx.x, lane = t & 31, warp = t >> 5;
    int wr = warp >> 1, wc = warp & 1;
    int base = blockIdx.x * 128;
    int r = lane >> 2, c = lane & 3;

    if (t < D) sbias[t] = bself[t] + bneigh[t] + bneigh2[t];
    float acc[16][4];
#pragma unroll
    for (int i = 0; i < 16; i++)
#pragma unroll
        for (int q = 0; q < 4; q++) acc[i][q] = 0.f;

    for (int s3 = 0; s3 < 3; s3++) {
        const __half* W = s3 == 0 ? g_Wselfh : s3 == 1 ? g_Wneighh : g_Wneigh2h;
        __syncthreads();
        {
            int row = t >> 1, k0 = (t & 1) * 64;
            int node = base + row;
            __half* ap = As + row * PH + k0;
            if (node >= NN) {
                for (int k = 0; k < 64; k += 8) *(uint4*)(ap + k) = make_uint4(0, 0, 0, 0);
            } else if (s3 == 0) {
                const float* fr = feat + (size_t)node * D + k0;
#pragma unroll
                for (int k = 0; k < 64; k += 8) {
                    float4 v0 = *(const float4*)(fr + k);
                    float4 v1 = *(const float4*)(fr + k + 4);
                    *(uint4*)(ap + k) = make_uint4(pk2(v0.x, v0.y), pk2(v0.z, v0.w),
                                                   pk2(v1.x, v1.y), pk2(v1.z, v1.w));
                }
            } else {
                const __half* Xh = (s3 == 1 ? g_neigh : g_neigh2) + (size_t)node * D + k0;
#pragma unroll
                for (int k = 0; k < 64; k += 8)
                    *(uint4*)(ap + k) = *(const uint4*)(Xh + k);
            }
        }
        stage_Bh(Bs, W, t);
        __syncthreads();
        gemm_tile(As, Bs, wr, wc, lane, acc);
    }
#pragma unroll
    for (int mi = 0; mi < 2; mi++)
#pragma unroll
        for (int ni = 0; ni < 8; ni++) {
            int col = wc * 64 + ni * 8 + 2 * c;
            acc[mi * 8 + ni][0] += sbias[col];
            acc[mi * 8 + ni][1] += sbias[col + 1];
            acc[mi * 8 + ni][2] += sbias[col];
            acc[mi * 8 + ni][3] += sbias[col + 1];
        }

    for (int li = 0; li < 2; li++) {
        __syncthreads();
#pragma unroll
        for (int mi = 0; mi < 2; mi++)
#pragma unroll
            for (int h = 0; h < 2; h++) {
                int row = wr * 32 + mi * 16 + r + h * 8;
#pragma unroll
                for (int ni = 0; ni < 8; ni++) {
                    int col = wc * 64 + ni * 8 + 2 * c;
                    *(uint32_t*)(As + row * PH + col) =
                        pk2(gelu_f(acc[mi * 8 + ni][h * 2 + 0]),
                            gelu_f(acc[mi * 8 + ni][h * 2 + 1]));
                }
            }
        stage_Bh(Bs, g_Wmlph + (size_t)li * D * D, t);
        if (t < D) sb2[t] = bmlp[li * D + t];
        __syncthreads();
        gemm_tile(As, Bs, wr, wc, lane, acc);   // acc += gelu(rst) @ W^T  (in place)
#pragma unroll
        for (int mi = 0; mi < 2; mi++)
#pragma unroll
            for (int ni = 0; ni < 8; ni++) {
                int col = wc * 64 + ni * 8 + 2 * c;
                acc[mi * 8 + ni][0] += sb2[col];
                acc[mi * 8 + ni][1] += sb2[col + 1];
                acc[mi * 8 + ni][2] += sb2[col];
                acc[mi * 8 + ni][3] += sb2[col + 1];
            }
    }
#pragma unroll
    for (int mi = 0; mi < 2; mi++)
#pragma unroll
        for (int h = 0; h < 2; h++) {
            int node = base + wr * 32 + mi * 16 + r + h * 8;
            if (node < NN) {
#pragma unroll
                for (int ni = 0; ni < 8; ni++) {
                    int col = wc * 64 + ni * 8 + 2 * c;
                    *(float2*)(out + (size_t)node * D + col) =
                        make_float2(acc[mi * 8 + ni][h * 2 + 0], acc[mi * 8 + ni][h * 2 + 1]);
                }
            }
        }
}

// ---------------- launch (forked graph: CSR build || node GEMMs) ----------------
extern "C" void kernel_launch(void* const* d_in, const int* in_sizes, int n_in,
                              void* d_out, int out_size) {
    const float* feat = (const float*)d_in[0];
    const int* src = (const int*)d_in[1];
    const int* dst = (const int*)d_in[2];
    const float* Wasrc = (const float*)d_in[3];
    const float* basrc = (const float*)d_in[4];
    const float* Wadst = (const float*)d_in[5];
    const float* badst = (const float*)d_in[6];
    const float* Wasub = (const float*)d_in[7];
    const float* basub = (const float*)d_in[8];
    const float* Wamul = (const float*)d_in[9];
    const float* bamul = (const float*)d_in[10];
    const float* Waout = (const float*)d_in[11];
    const float* baout = (const float*)d_in[12];
    const float* Wpool = (const float*)d_in[13];
    const float* bpool = (const float*)d_in[14];
    const float* Wpool2 = (const float*)d_in[15];
    const float* bpool2 = (const float*)d_in[16];
    const float* Wself = (const float*)d_in[17];
    const float* bself = (const float*)d_in[18];
    const float* Wneigh = (const float*)d_in[19];
    const float* bneigh = (const float*)d_in[20];
    const float* Wneigh2 = (const float*)d_in[21];
    const float* bneigh2 = (const float*)d_in[22];
    const float* Wmlp = (const float*)d_in[23];
    const float* bmlp = (const float*)d_in[24];
    float* out = (float*)d_out;

    static cudaStream_t s1 = nullptr;
    static cudaEvent_t evFork = nullptr, evJoin = nullptr;
    if (s1 == nullptr) {
        cudaStreamCreateWithFlags(&s1, cudaStreamNonBlocking);
        cudaEventCreateWithFlags(&evFork, cudaEventDisableTiming);
        cudaEventCreateWithFlags(&evJoin, cudaEventDisableTiming);
    }

    const int SMEM_AB = 2 * D * PH * (int)sizeof(__half);          // 69632
    const int SMEM_EDGE = SMEM_AB + 128 * 8 * (int)sizeof(float);  // 73728
    cudaFuncSetAttribute(node_mma, cudaFuncAttributeMaxDynamicSharedMemorySize, SMEM_AB);
    cudaFuncSetAttribute(edge_mma, cudaFuncAttributeMaxDynamicSharedMemorySize, SMEM_EDGE);
    cudaFuncSetAttribute(final_mma, cudaFuncAttributeMaxDynamicSharedMemorySize, SMEM_AB);

    prep_kernel<<<NBLK, 256>>>(Wasrc, Wadst, Wasub, Wamul, Wpool, Wpool2, Wself,
                               Wneigh, Wneigh2, Wmlp, basrc, badst, basub, bamul);

    cudaEventRecord(evFork, 0);
    cudaStreamWaitEvent(s1, evFork, 0);
    node_mma<<<(NN + 127) / 128, 256, SMEM_AB, s1>>>(feat, bpool, bpool2);
    cudaEventRecord(evJoin, s1);

    deg_kernel<<<(NE + 255) / 256, 256>>>(dst);
    scan1_kernel<<<NBLK, 256>>>();
    scan2_kernel<<<1, 256>>>();
    scan3_kernel<<<NBLK, 256>>>();
    fill_kernel<<<(NE + 255) / 256, 256>>>(src, dst);

    cudaStreamWaitEvent(0, evJoin, 0);
    edge_mma<<<NE / 128, 256, SMEM_EDGE>>>(Waout, baout);
    agg_kernel<<<(NN * 32 + 255) / 256, 256>>>();
    final_mma<<<(NN + 127) / 128, 256, SMEM_AB>>>(feat, bself, bneigh, bneigh2, bmlp, out);
}